// round 16
// baseline (speedup 1.0000x reference)
#include <cuda_runtime.h>
#include <cuda_fp16.h>
#include <math.h>
#include <stdint.h>

// N=50000, P=1.6M, F=128, G=16, H=32, HID1=256, HID2=128, IN=288 (vec_q==0 dropped)
#define NMAX 50000

__device__ float  g_acc[NMAX * 64];             // [n][0:16]=Gsum, [16:64]=GVsum(d,g)
__device__ __half g_Mh[(size_t)NMAX * 512];     // M = emb@agh, fp16
__device__ __half g_msgh[(size_t)NMAX * 288];   // MLP input fp16
__device__ __half g_h1h[(size_t)NMAX * 256];    // layer1 activations fp16
__device__ __half g_embh[(size_t)NMAX * 128];   // emb fp16
__device__ __half g_aghh[512 * 128];            // agh^T fp16 [n=512][k=128]
__device__ __half g_w1h[256 * 288];             // W1^T fp16 [n][k]
__device__ __half g_w2h[128 * 256];             // W2^T fp16 [n][k]
__device__ __half g_w3h[136 * 128];             // W3^T fp16 [n][k], n padded

__device__ __forceinline__ float gelu_exact(float x) {
    return 0.5f * x * (1.0f + erff(x * 0.70710678118654752f));
}
__device__ __forceinline__ void mma_f16(float d[4], const uint32_t a[4],
                                        const uint32_t b[2]) {
    asm volatile(
        "mma.sync.aligned.m16n8k16.row.col.f32.f16.f16.f32 "
        "{%0,%1,%2,%3}, {%4,%5,%6,%7}, {%8,%9}, {%0,%1,%2,%3};"
        : "+f"(d[0]), "+f"(d[1]), "+f"(d[2]), "+f"(d[3])
        : "r"(a[0]), "r"(a[1]), "r"(a[2]), "r"(a[3]), "r"(b[0]), "r"(b[1]));
}
__device__ __forceinline__ uint32_t h2u(const __half* p) {
    return *reinterpret_cast<const uint32_t*>(p);
}
__device__ __forceinline__ void cpa16(void* s, const void* g) {
    uint32_t sp = (uint32_t)__cvta_generic_to_shared(s);
    asm volatile("cp.async.cg.shared.global [%0], [%1], 16;" :: "r"(sp), "l"(g));
}
#define CP_COMMIT() asm volatile("cp.async.commit_group;" ::: "memory")
#define CP_WAIT1()  asm volatile("cp.async.wait_group 1;" ::: "memory")
#define CP_WAIT0()  asm volatile("cp.async.wait_group 0;" ::: "memory")

// ---------------------------------------------------------------------------
// Launch 1: prep = fp16 conversions + zero g_acc
// ---------------------------------------------------------------------------
#define CVT_W (512 * 128 + 256 * 288 + 128 * 256 + 136 * 128)
__global__ void k_prep(const float* __restrict__ agh, const float* __restrict__ W1,
                       const float* __restrict__ W2, const float* __restrict__ W3,
                       const float* __restrict__ emb, int N) {
    int i = blockIdx.x * blockDim.x + threadIdx.x;
    if (i < 512 * 128) {
        int n = i >> 7, k = i & 127;
        g_aghh[i] = __float2half(agh[(size_t)k * 512 + n]);
        return;
    }
    i -= 512 * 128;
    if (i < 256 * 288) {
        int n = i / 288, k = i - n * 288;
        g_w1h[i] = __float2half(W1[(size_t)k * 256 + n]);
        return;
    }
    i -= 256 * 288;
    if (i < 128 * 256) {
        int n = i >> 8, k = i & 255;
        g_w2h[i] = __float2half(W2[(size_t)k * 128 + n]);
        return;
    }
    i -= 128 * 256;
    if (i < 136 * 128) {
        int n = i >> 7, k = i & 127;
        g_w3h[i] = (n < 130) ? __float2half(W3[(size_t)k * 130 + n]) : __float2half(0.f);
        return;
    }
    i -= 136 * 128;
    if (i < N * 128) { g_embh[i] = __float2half(emb[i]); return; }
    i -= N * 128;
    if (i < N * 16)
        reinterpret_cast<float4*>(g_acc)[i] = make_float4(0.f, 0.f, 0.f, 0.f);
}

// ---------------------------------------------------------------------------
// Launch 2: MEGA = interleaved pair-scatter blocks + M-GEMM blocks.
// Blocks [0, 2*GB): odd = GEMM CTA (id = bid>>1), even = scatter (id = bid>>1).
// Blocks >= 2*GB: scatter (id = bid - GB).
// GEMM: 64 atoms/CTA, 512 thr, k-chunks of 16 double-buffered, writes g_Mh.
// smem 66560 B -> up to 3 blocks/SM so scatter co-schedules with GEMM.
// ---------------------------------------------------------------------------
#define MG_XS 0                          // Xs: 64*136 halves = 17408 B
#define MG_W0 17408                      // Wb0: 512*24*2 = 24576 B
#define MG_W1 (17408 + 24576)            // 41984
#define MG_SMEM (41984 + 24576)          // 66560 B
#define GXP 136
#define GBP2 24

__global__ void __launch_bounds__(512, 1) k_mega(
    const int* __restrict__ idxj, const float* __restrict__ gs,
    const float* __restrict__ gv, int P, int GB, int N) {
    int bid = blockIdx.x;
    bool is_gemm = (bid < 2 * GB) && (bid & 1);

    if (!is_gemm) {
        // -------- scatter role: 2 quads / thread --------
        int sid = (bid < 2 * GB) ? (bid >> 1) : (bid - GB);
        long long total = (long long)P * 16;
        long long q1 = (long long)sid * 1024 + threadIdx.x;
        long long q2 = q1 + 512;
        float4 v1, v2;
        float *d1 = 0, *d2 = 0;
        if (q1 < total) {
            int p = (int)(q1 >> 4), c = (int)(q1 & 15);
            int n = idxj[p];
            if (c < 4) {
                v1 = *reinterpret_cast<const float4*>(gs + (size_t)p * 16 + c * 4);
                d1 = g_acc + (size_t)n * 64 + c * 4;
            } else {
                v1 = *reinterpret_cast<const float4*>(gv + (size_t)p * 48 + (c - 4) * 4);
                d1 = g_acc + (size_t)n * 64 + 16 + (c - 4) * 4;
            }
        }
        if (q2 < total) {
            int p = (int)(q2 >> 4), c = (int)(q2 & 15);
            int n = idxj[p];
            if (c < 4) {
                v2 = *reinterpret_cast<const float4*>(gs + (size_t)p * 16 + c * 4);
                d2 = g_acc + (size_t)n * 64 + c * 4;
            } else {
                v2 = *reinterpret_cast<const float4*>(gv + (size_t)p * 48 + (c - 4) * 4);
                d2 = g_acc + (size_t)n * 64 + 16 + (c - 4) * 4;
            }
        }
        if (d1)
            asm volatile("red.global.add.v4.f32 [%0], {%1,%2,%3,%4};"
                         :: "l"(d1), "f"(v1.x), "f"(v1.y), "f"(v1.z), "f"(v1.w) : "memory");
        if (d2)
            asm volatile("red.global.add.v4.f32 [%0], {%1,%2,%3,%4};"
                         :: "l"(d2), "f"(v2.x), "f"(v2.y), "f"(v2.z), "f"(v2.w) : "memory");
        return;
    }

    // -------- GEMM role: M[64 x 512] = emb[64 x 128] @ agh[128 x 512] --------
    extern __shared__ char smraw[];
    __half* Xs  = reinterpret_cast<__half*>(smraw + MG_XS);
    __half* Wb0 = reinterpret_cast<__half*>(smraw + MG_W0);
    __half* Wb1 = reinterpret_cast<__half*>(smraw + MG_W1);
    int a0 = (bid >> 1) * 64;
    int tid = threadIdx.x;
    int lane = tid & 31, warp = tid >> 5;
    int gid = lane >> 2, tig = lane & 3;
    int wm = warp >> 3, wn = warp & 7;   // 2m x 8n: warp = 32 rows x 64 cols

    // group0: Xs + chunk0; group1: chunk1
    for (int i = tid; i < 64 * 16; i += 512) {
        int r = i >> 4, u = i & 15;
        int n = a0 + r; if (n >= N) n = N - 1;
        cpa16(Xs + r * GXP + u * 8, g_embh + (size_t)n * 128 + u * 8);
    }
    for (int i = tid; i < 512 * 2; i += 512) {
        int r = i >> 1, u = i & 1;
        cpa16(Wb0 + r * GBP2 + u * 8, g_aghh + (size_t)r * 128 + u * 8);
    }
    CP_COMMIT();
    for (int i = tid; i < 512 * 2; i += 512) {
        int r = i >> 1, u = i & 1;
        cpa16(Wb1 + r * GBP2 + u * 8, g_aghh + (size_t)r * 128 + 16 + u * 8);
    }
    CP_COMMIT();

    float acc[2][8][4];
    #pragma unroll
    for (int mt = 0; mt < 2; mt++)
        #pragma unroll
        for (int nt = 0; nt < 8; nt++)
            #pragma unroll
            for (int e = 0; e < 4; e++) acc[mt][nt][e] = 0.f;

    for (int c = 0; c < 8; c++) {
        CP_WAIT1();
        __syncthreads();
        __half* wb = (c & 1) ? Wb1 : Wb0;
        int kg = c * 16;
        uint32_t A[2][4];
        #pragma unroll
        for (int mt = 0; mt < 2; mt++) {
            int row = 32 * wm + 16 * mt + gid;
            A[mt][0] = h2u(&Xs[row * GXP + kg + tig * 2]);
            A[mt][1] = h2u(&Xs[(row + 8) * GXP + kg + tig * 2]);
            A[mt][2] = h2u(&Xs[row * GXP + kg + tig * 2 + 8]);
            A[mt][3] = h2u(&Xs[(row + 8) * GXP + kg + tig * 2 + 8]);
        }
        #pragma unroll
        for (int nt = 0; nt < 8; nt++) {
            int nn = 64 * wn + 8 * nt + gid;
            uint32_t B[2];
            B[0] = h2u(&wb[nn * GBP2 + tig * 2]);
            B[1] = h2u(&wb[nn * GBP2 + tig * 2 + 8]);
            mma_f16(acc[0][nt], A[0], B);
            mma_f16(acc[1][nt], A[1], B);
        }
        __syncthreads();
        if (c + 2 < 8) {
            __half* dst = (c & 1) ? Wb1 : Wb0;
            for (int i = tid; i < 512 * 2; i += 512) {
                int r = i >> 1, u = i & 1;
                cpa16(dst + r * GBP2 + u * 8,
                      g_aghh + (size_t)r * 128 + (c + 2) * 16 + u * 8);
            }
        }
        CP_COMMIT();
    }

    // write M -> g_Mh (fp16)
    #pragma unroll
    for (int mt = 0; mt < 2; mt++) {
        int r0 = 32 * wm + 16 * mt + gid;
        int n0 = a0 + r0, n1 = n0 + 8;
        #pragma unroll
        for (int nt = 0; nt < 8; nt++) {
            int col = 64 * wn + 8 * nt + 2 * tig;
            if (n0 < N)
                *reinterpret_cast<__half2*>(&g_Mh[(size_t)n0 * 512 + col]) =
                    __floats2half2_rn(acc[mt][nt][0], acc[mt][nt][1]);
            if (n1 < N)
                *reinterpret_cast<__half2*>(&g_Mh[(size_t)n1 * 512 + col]) =
                    __floats2half2_rn(acc[mt][nt][2], acc[mt][nt][3]);
        }
    }
}

// ---------------------------------------------------------------------------
// Launch 3: assemble msg from g_acc + g_Mh + emb. 64 atoms/CTA, 512 thr.
// smem: Ms 64x520h | sa 64x64 f32 | Wgf f32 | Xe 64x136h = 108544 B (2/SM)
// ---------------------------------------------------------------------------
#define AS_MS 0
#define AS_SA 66560
#define AS_WG (66560 + 16384)
#define AS_XE (AS_WG + 8192)
#define AS_SMEM (AS_XE + 17408)   // 108544
#define GMP 520

__global__ void __launch_bounds__(512, 2) k_asm(
    const float* __restrict__ q, const float* __restrict__ Wgf, int N) {
    extern __shared__ char smraw[];
    __half* Ms   = reinterpret_cast<__half*>(smraw + AS_MS);
    float*  sa   = reinterpret_cast<float*>(smraw + AS_SA);
    float*  Wgfs = reinterpret_cast<float*>(smraw + AS_WG);
    __half* Xe   = reinterpret_cast<__half*>(smraw + AS_XE);
    int a0 = blockIdx.x * 64;
    int tid = threadIdx.x;

    for (int i = tid; i < 64 * 64; i += 512) {      // Ms: 64 rows x 64 cpa16
        int r = i >> 6, u = i & 63;
        int n = a0 + r; if (n >= N) n = N - 1;
        cpa16(Ms + r * GMP + u * 8, g_Mh + (size_t)n * 512 + u * 8);
    }
    for (int i = tid; i < 64 * 16; i += 512) {
        int r = i >> 4, c4 = i & 15;
        int n = a0 + r; if (n >= N) n = N - 1;
        cpa16(sa + r * 64 + c4 * 4, g_acc + (size_t)n * 64 + c4 * 4);
    }
    for (int i = tid; i < 16 * 32; i += 512) {
        cpa16(Wgfs + i * 4, Wgf + i * 4);
    }
    for (int i = tid; i < 64 * 16; i += 512) {
        int r = i >> 4, u = i & 15;
        int n = a0 + r; if (n >= N) n = N - 1;
        cpa16(Xe + r * GXP + u * 8, g_embh + (size_t)n * 128 + u * 8);
    }
    CP_COMMIT(); CP_WAIT0();
    __syncthreads();

    for (int idx = tid; idx < 64 * 64; idx += 512) {
        int r = idx >> 6, f2 = idx & 63;
        int n = a0 + r;
        if (n >= N) continue;
        int f = 2 * f2;
        float m0 = 0.f, m1 = 0.f;
        #pragma unroll
        for (int g = 0; g < 16; g++) {
            float s = sa[r * 64 + g];
            m0 += s * Wgfs[g * 128 + f];
            m1 += s * Wgfs[g * 128 + f + 1];
        }
        float e0 = __half2float(Xe[r * GXP + f]);
        float e1 = __half2float(Xe[r * GXP + f + 1]);
        float qq = q[n];
        __half* msg = g_msgh + (size_t)n * 288;
        *reinterpret_cast<__half2*>(&msg[f])       = __floats2half2_rn(e0 * m0, e1 * m1);
        *reinterpret_cast<__half2*>(&msg[160 + f]) = __floats2half2_rn(qq * m0, qq * m1);
    }
    for (int idx = tid; idx < 64 * 32; idx += 512) {
        int r = idx >> 5, h = idx & 31;
        int n = a0 + r;
        if (n >= N) continue;
        float v0 = 0.f, v1 = 0.f, v2 = 0.f;
        #pragma unroll
        for (int g = 0; g < 16; g++) {
            float Mv = __half2float(Ms[r * GMP + g * 32 + h]);
            v0 += sa[r * 64 + 16 + g] * Mv;
            v1 += sa[r * 64 + 32 + g] * Mv;
            v2 += sa[r * 64 + 48 + g] * Mv;
        }
        float sq = v0 * v0 + v1 * v1 + v2 * v2;
        g_msgh[(size_t)n * 288 + 128 + h] = __float2half((sq > 0.f) ? sqrtf(sq) : 0.f);
    }
}

// ---------------------------------------------------------------------------
// Launch 4 (PROFILED): Layer 1, fp16, 128-atom tiles (R14 config, 43.8us).
// ---------------------------------------------------------------------------
#define L1KP 296
#define L1_OX (256 * L1KP)
#define L1_SMEM ((L1_OX + 128 * L1KP) * 2)

__global__ void __launch_bounds__(512, 1) k_l1(const float* __restrict__ b1, int N) {
    extern __shared__ __half smh[];
    __half* W  = smh;
    __half* Xs = smh + L1_OX;
    int tid = threadIdx.x;
    int lane = tid & 31, warp = tid >> 5;
    int gid = lane >> 2, tig = lane & 3;
    int wm = warp >> 2, wn = warp & 3;

    for (int i = tid; i < 256 * 36; i += 512) {
        int r = i / 36, u = i - r * 36;
        cpa16(W + r * L1KP + u * 8, g_w1h + (size_t)r * 288 + u * 8);
    }
    CP_COMMIT();

    int tiles = (N + 127) >> 7;
    for (int t = blockIdx.x; t < tiles; t += gridDim.x) {
        int a0 = t * 128;
        __syncthreads();
        for (int i = tid; i < 128 * 36; i += 512) {
            int r = i / 36, u = i - r * 36;
            int n = a0 + r; if (n >= N) n = N - 1;
            cpa16(Xs + r * L1KP + u * 8, g_msgh + (size_t)n * 288 + u * 8);
        }
        CP_COMMIT(); CP_WAIT0();
        __syncthreads();

        float acc[2][8][4];
        #pragma unroll
        for (int mt = 0; mt < 2; mt++)
            #pragma unroll
            for (int nt = 0; nt < 8; nt++)
                #pragma unroll
                for (int e = 0; e < 4; e++) acc[mt][nt][e] = 0.f;

        #pragma unroll 2
        for (int kg = 0; kg < 288; kg += 16) {
            uint32_t A[2][4];
            #pragma unroll
            for (int mt = 0; mt < 2; mt++) {
                int row = 32 * wm + 16 * mt + gid;
                A[mt][0] = h2u(&Xs[row * L1KP + kg + tig * 2]);
                A[mt][1] = h2u(&Xs[(row + 8) * L1KP + kg + tig * 2]);
                A[mt][2] = h2u(&Xs[row * L1KP + kg + tig * 2 + 8]);
                A[mt][3] = h2u(&Xs[(row + 8) * L1KP + kg + tig * 2 + 8]);
            }
            #pragma unroll
            for (int nt = 0; nt < 8; nt++) {
                int nn = 64 * wn + 8 * nt + gid;
                uint32_t B[2];
                B[0] = h2u(&W[nn * L1KP + kg + tig * 2]);
                B[1] = h2u(&W[nn * L1KP + kg + tig * 2 + 8]);
                mma_f16(acc[0][nt], A[0], B);
                mma_f16(acc[1][nt], A[1], B);
            }
        }

        #pragma unroll
        for (int mt = 0; mt < 2; mt++) {
            int row0 = 32 * wm + 16 * mt + gid;
            int n0 = a0 + row0, n1 = n0 + 8;
            #pragma unroll
            for (int nt = 0; nt < 8; nt++) {
                int col = 64 * wn + 8 * nt + 2 * tig;
                float bb0 = b1[col], bb1 = b1[col + 1];
                if (n0 < N)
                    *reinterpret_cast<__half2*>(&g_h1h[(size_t)n0 * 256 + col]) =
                        __floats2half2_rn(gelu_exact(acc[mt][nt][0] + bb0),
                                          gelu_exact(acc[mt][nt][1] + bb1));
                if (n1 < N)
                    *reinterpret_cast<__half2*>(&g_h1h[(size_t)n1 * 256 + col]) =
                        __floats2half2_rn(gelu_exact(acc[mt][nt][2] + bb0),
                                          gelu_exact(acc[mt][nt][3] + bb1));
            }
        }
    }
}

// ---------------------------------------------------------------------------
// Launch 5: merged Layers 2+3, double-buffered acts (R15 config).
// ---------------------------------------------------------------------------
#define L2KP 264
#define L3KP 136
#define M23_W2 0
#define M23_W3 (128 * L2KP)
#define M23_X0 (M23_W3 + 136 * L3KP)
#define M23_X1 (M23_X0 + 64 * L2KP)
#define M23_H2 (M23_X1 + 64 * L2KP)
#define M23_SMEM ((M23_H2 + 64 * L3KP) * 2)

__device__ __forceinline__ void l23_stage(__half* dst, int t, int N) {
    int a0 = t * 64;
    for (int i = threadIdx.x; i < 64 * 32; i += 512) {
        int r = i >> 5, u = i & 31;
        int n = a0 + r; if (n >= N) n = N - 1;
        cpa16(dst + r * L2KP + u * 8, g_h1h + (size_t)n * 256 + u * 8);
    }
}

__global__ void __launch_bounds__(512, 1) k_l23(const float* __restrict__ b2,
                                                const float* __restrict__ b3,
                                                float* __restrict__ out, int N) {
    extern __shared__ __half smh[];
    __half* W2 = smh + M23_W2;
    __half* W3 = smh + M23_W3;
    __half* X0 = smh + M23_X0;
    __half* X1 = smh + M23_X1;
    __half* H2 = smh + M23_H2;
    int tid = threadIdx.x;
    int lane = tid & 31, warp = tid >> 5;
    int gid = lane >> 2, tig = lane & 3;
    int wm = warp >> 3, wn = warp & 7;

    for (int i = tid; i < 128 * 32; i += 512) {
        int r = i >> 5, u = i & 31;
        cpa16(W2 + r * L2KP + u * 8, g_w2h + (size_t)r * 256 + u * 8);
    }
    for (int i = tid; i < 136 * 16; i += 512) {
        int r = i >> 4, u = i & 15;
        cpa16(W3 + r * L3KP + u * 8, g_w3h + (size_t)r * 128 + u * 8);
    }
    CP_COMMIT();

    int tiles = (N + 63) >> 6;
    if (blockIdx.x < tiles) l23_stage(X0, blockIdx.x, N);
    CP_COMMIT();
    if (blockIdx.x + 148 < tiles) l23_stage(X1, blockIdx.x + 148, N);
    CP_COMMIT();

    size_t dq_off = (size_t)N * 128;
    size_t f_off = dq_off + (size_t)N;
    int it = 0;
    for (int t = blockIdx.x; t < tiles; t += 148, it++) {
        CP_WAIT1();
        __syncthreads();
        __half* Xs = (it & 1) ? X1 : X0;
        int a0 = t * 64;

        float acc[2][2][4];
        #pragma unroll
        for (int mt = 0; mt < 2; mt++)
            #pragma unroll
            for (int nt = 0; nt < 2; nt++)
                #pragma unroll
                for (int e = 0; e < 4; e++) acc[mt][nt][e] = 0.f;

        #pragma unroll 2
        for (int kg = 0; kg < 256; kg += 16) {
            uint32_t A[2][4];
            #pragma unroll
            for (int mt = 0; mt < 2; mt++) {
                int row = 32 * wm + 16 * mt + gid;
                A[mt][0] = h2u(&Xs[row * L2KP + kg + tig * 2]);
                A[mt][1] = h2u(&Xs[(row + 8) * L2KP + kg + tig * 2]);
                A[mt][2] = h2u(&Xs[row * L2KP + kg + tig * 2 + 8]);
                A[mt][3] = h2u(&Xs[(row + 8) * L2KP + kg + tig * 2 + 8]);
            }
            #pragma unroll
            for (int nt = 0; nt < 2; nt++) {
                int nn = 16 * wn + 8 * nt + gid;
                uint32_t B[2];
                B[0] = h2u(&W2[nn * L2KP + kg + tig * 2]);
                B[1] = h2u(&W2[nn * L2KP + kg + tig * 2 + 8]);
                mma_f16(acc[0][nt], A[0], B);
                mma_f16(acc[1][nt], A[1], B);
            }
        }
        #pragma unroll
        for (int mt = 0; mt < 2; mt++) {
            int row0 = 32 * wm + 16 * mt + gid;
            #pragma unroll
            for (int nt = 0; nt < 2; nt++) {
                int col = 16 * wn + 8 * nt + 2 * tig;
                float bb0 = b2[col], bb1 = b2[col + 1];
                *reinterpret_cast<__half2*>(&H2[row0 * L3KP + col]) =
                    __floats2half2_rn(gelu_exact(acc[mt][nt][0] + bb0),
                                      gelu_exact(acc[mt][nt][1] + bb1));
                *reinterpret_cast<__half2*>(&H2[(row0 + 8) * L3KP + col]) =
                    __floats2half2_rn(gelu_exact(acc[mt][nt][2] + bb0),
                                      gelu_exact(acc[mt][nt][3] + bb1));
            }
        }
        __syncthreads();
        int tn = t + 2 * 148;
        if (tn < tiles) l23_stage(Xs, tn, N);
        CP_COMMIT();

        float d3[5][4];
        #pragma unroll
        for (int tt = 0; tt < 5; tt++)
            #pragma unroll
            for (int e = 0; e < 4; e++) d3[tt][e] = 0.f;

        #pragma unroll
        for (int tt = 0; tt < 5; tt++) {
            int tw = warp + 16 * tt;
            if (tw >= 68) break;
            int m0 = 16 * (tw & 3), n0 = 8 * (tw >> 2);
            #pragma unroll
            for (int kg = 0; kg < 128; kg += 16) {
                uint32_t A[4], B[2];
                A[0] = h2u(&H2[(m0 + gid) * L3KP + kg + tig * 2]);
                A[1] = h2u(&H2[(m0 + 8 + gid) * L3KP + kg + tig * 2]);
                A[2] = h2u(&H2[(m0 + gid) * L3KP + kg + tig * 2 + 8]);
                A[3] = h2u(&H2[(m0 + 8 + gid) * L3KP + kg + tig * 2 + 8]);
                B[0] = h2u(&W3[(n0 + gid) * L3KP + kg + tig * 2]);
                B[1] = h2u(&W3[(n0 + gid) * L3KP + kg + tig * 2 + 8]);
                mma_f16(d3[tt], A, B);
            }
        }

        #pragma unroll
        for (int tt = 0; tt < 5; tt++) {
            int tw = warp + 16 * tt;
            if (tw >= 68) break;
            int m0 = 16 * (tw & 3), n0 = 8 * (tw >> 2);
            #pragma unroll
            for (int e = 0; e < 4; e++) {
                int row = m0 + gid + ((e >> 1) ? 8 : 0);
                int j = n0 + 2 * tig + (e & 1);
                int n = a0 + row;
                if (n >= N || j >= 130) continue;
                float v = d3[tt][e] + b3[j];
                if (j == 0)      out[dq_off + n] = v;
                else if (j == 1) out[f_off + n] = v;
                else             out[(size_t)n * 128 + (j - 2)] = v;
            }
        }
    }
}

// ---------------------------------------------------------------------------
extern "C" void kernel_launch(void* const* d_in, const int* in_sizes, int n_in,
                              void* d_out, int out_size) {
    const float* emb  = (const float*)d_in[0];
    const float* q    = (const float*)d_in[1];
    const int*   pidx = (const int*)d_in[2];
    const float* gs   = (const float*)d_in[3];
    const float* gv   = (const float*)d_in[4];
    const float* agh  = (const float*)d_in[5];
    const float* Wgf  = (const float*)d_in[6];
    const float* W1   = (const float*)d_in[7];
    const float* b1   = (const float*)d_in[8];
    const float* W2   = (const float*)d_in[9];
    const float* b2   = (const float*)d_in[10];
    const float* W3   = (const float*)d_in[11];
    const float* b3   = (const float*)d_in[12];
    float* out = (float*)d_out;

    int N = in_sizes[0] / 128;
    int P = in_sizes[2] / 2;
    if (N > NMAX) N = NMAX;
    const int* idxj = pidx + P;

    // 1: prep (conversions + zero)
    int prep_tot = CVT_W + N * 128 + N * 16;
    k_prep<<<(prep_tot + 255) / 256, 256>>>(agh, W1, W2, W3, emb, N);

    // 2: mega (scatter || M-GEMM)
    long long Q = (long long)P * 16;
    int SBLK = (int)((Q + 1023) / 1024);
    int GB = (N + 63) / 64;
    cudaFuncSetAttribute(k_mega, cudaFuncAttributeMaxDynamicSharedMemorySize, MG_SMEM);
    k_mega<<<SBLK + GB, 512, MG_SMEM>>>(idxj, gs, gv, P, GB, N);

    // 3: assemble msg
    cudaFuncSetAttribute(k_asm, cudaFuncAttributeMaxDynamicSharedMemorySize, AS_SMEM);
    k_asm<<<GB, 512, AS_SMEM>>>(q, Wgf, N);

    // 4 (profiled): layer 1 (R14 config)
    cudaFuncSetAttribute(k_l1, cudaFuncAttributeMaxDynamicSharedMemorySize, L1_SMEM);
    k_l1<<<148, 512, L1_SMEM>>>(b1, N);

    // 5: merged layers 2+3 (R15 config)
    cudaFuncSetAttribute(k_l23, cudaFuncAttributeMaxDynamicSharedMemorySize, M23_SMEM);
    k_l23<<<148, 512, M23_SMEM>>>(b2, b3, out, N);
}

// round 17
// speedup vs baseline: 1.7373x; 1.7373x over previous
#include <cuda_runtime.h>
#include <cuda_fp16.h>
#include <math.h>
#include <stdint.h>

// N=50000, P=1.6M, F=128, G=16, H=32, HID1=256, HID2=128, IN=288 (vec_q==0 dropped)
#define NMAX 50000

__device__ float  g_acc[NMAX * 64];             // [n][0:16]=Gsum, [16:64]=GVsum(d,g)
__device__ __half g_msgh[(size_t)NMAX * 288];   // MLP input fp16
__device__ __half g_h1h[(size_t)NMAX * 256];    // layer1 activations fp16
__device__ __half g_embh[(size_t)NMAX * 128];   // emb fp16
__device__ __half g_aghh[512 * 128];            // agh^T fp16 [n=512][k=128]
__device__ __half g_w1h[256 * 288];             // W1^T fp16 [n][k]
__device__ __half g_w2h[128 * 256];             // W2^T fp16 [n][k]
__device__ __half g_w3h[136 * 128];             // W3^T fp16 [n][k], n padded

__device__ __forceinline__ float gelu_exact(float x) {
    return 0.5f * x * (1.0f + erff(x * 0.70710678118654752f));
}
__device__ __forceinline__ void mma_f16(float d[4], const uint32_t a[4],
                                        const uint32_t b[2]) {
    asm volatile(
        "mma.sync.aligned.m16n8k16.row.col.f32.f16.f16.f32 "
        "{%0,%1,%2,%3}, {%4,%5,%6,%7}, {%8,%9}, {%0,%1,%2,%3};"
        : "+f"(d[0]), "+f"(d[1]), "+f"(d[2]), "+f"(d[3])
        : "r"(a[0]), "r"(a[1]), "r"(a[2]), "r"(a[3]), "r"(b[0]), "r"(b[1]));
}
__device__ __forceinline__ uint32_t h2u(const __half* p) {
    return *reinterpret_cast<const uint32_t*>(p);
}
__device__ __forceinline__ void cpa16(void* s, const void* g) {
    uint32_t sp = (uint32_t)__cvta_generic_to_shared(s);
    asm volatile("cp.async.cg.shared.global [%0], [%1], 16;" :: "r"(sp), "l"(g));
}
#define CP_COMMIT() asm volatile("cp.async.commit_group;" ::: "memory")
#define CP_WAIT1()  asm volatile("cp.async.wait_group 1;" ::: "memory")
#define CP_WAIT0()  asm volatile("cp.async.wait_group 0;" ::: "memory")

// ---------------------------------------------------------------------------
// Launch 1: zero pair accumulators
// ---------------------------------------------------------------------------
__global__ void k_zero(int N) {
    int i = blockIdx.x * blockDim.x + threadIdx.x;
    if (i < N * 16)
        reinterpret_cast<float4*>(g_acc)[i] = make_float4(0.f, 0.f, 0.f, 0.f);
}

// ---------------------------------------------------------------------------
// Launch 2: MERGED scatter (2 quads/thread, MLP=2) + fp16 conversions.
// ---------------------------------------------------------------------------
#define CVT_W (512 * 128 + 256 * 288 + 128 * 256 + 136 * 128)
__global__ void k_scatter_cvt(const int* __restrict__ idxj, const float* __restrict__ gs,
                              const float* __restrict__ gv, int P, int SB,
                              const float* __restrict__ agh, const float* __restrict__ W1,
                              const float* __restrict__ W2, const float* __restrict__ W3,
                              const float* __restrict__ emb, int N) {
    if (blockIdx.x < SB) {
        long long total = (long long)P * 16;
        long long q1 = (long long)blockIdx.x * 512 + threadIdx.x;
        long long q2 = q1 + 256;
        float4 v1, v2;
        float *d1 = 0, *d2 = 0;
        if (q1 < total) {
            int p = (int)(q1 >> 4), c = (int)(q1 & 15);
            int n = idxj[p];
            if (c < 4) {
                v1 = *reinterpret_cast<const float4*>(gs + (size_t)p * 16 + c * 4);
                d1 = g_acc + (size_t)n * 64 + c * 4;
            } else {
                v1 = *reinterpret_cast<const float4*>(gv + (size_t)p * 48 + (c - 4) * 4);
                d1 = g_acc + (size_t)n * 64 + 16 + (c - 4) * 4;
            }
        }
        if (q2 < total) {
            int p = (int)(q2 >> 4), c = (int)(q2 & 15);
            int n = idxj[p];
            if (c < 4) {
                v2 = *reinterpret_cast<const float4*>(gs + (size_t)p * 16 + c * 4);
                d2 = g_acc + (size_t)n * 64 + c * 4;
            } else {
                v2 = *reinterpret_cast<const float4*>(gv + (size_t)p * 48 + (c - 4) * 4);
                d2 = g_acc + (size_t)n * 64 + 16 + (c - 4) * 4;
            }
        }
        if (d1)
            asm volatile("red.global.add.v4.f32 [%0], {%1,%2,%3,%4};"
                         :: "l"(d1), "f"(v1.x), "f"(v1.y), "f"(v1.z), "f"(v1.w) : "memory");
        if (d2)
            asm volatile("red.global.add.v4.f32 [%0], {%1,%2,%3,%4};"
                         :: "l"(d2), "f"(v2.x), "f"(v2.y), "f"(v2.z), "f"(v2.w) : "memory");
        return;
    }
    int i = (blockIdx.x - SB) * blockDim.x + threadIdx.x;
    if (i < 512 * 128) {
        int n = i >> 7, k = i & 127;
        g_aghh[i] = __float2half(agh[(size_t)k * 512 + n]);
        return;
    }
    i -= 512 * 128;
    if (i < 256 * 288) {
        int n = i / 288, k = i - n * 288;
        g_w1h[i] = __float2half(W1[(size_t)k * 256 + n]);
        return;
    }
    i -= 256 * 288;
    if (i < 128 * 256) {
        int n = i >> 8, k = i & 255;
        g_w2h[i] = __float2half(W2[(size_t)k * 128 + n]);
        return;
    }
    i -= 128 * 256;
    if (i < 136 * 128) {
        int n = i >> 7, k = i & 127;
        g_w3h[i] = (n < 130) ? __float2half(W3[(size_t)k * 130 + n]) : __float2half(0.f);
        return;
    }
    i -= 136 * 128;
    if (i < N * 128) g_embh[i] = __float2half(emb[i]);
}

// ---------------------------------------------------------------------------
// Launch 3: fused GEMM-M + assemble, 64 atoms/CTA, 512 threads (R14/R15 config)
// ---------------------------------------------------------------------------
#define GXP 136
#define GBP 40
#define GMP 520
#define GA_XS_B 0
#define GA_SA_B 17408
#define GA_WG_B 33792
#define GA_WB_B 41984
#define GA_WB1_B 82944
#define GA_SMEM 123904

__global__ void __launch_bounds__(512, 1) k_gemm_assemble(
    const float* __restrict__ q, const float* __restrict__ Wgf, int N) {
    extern __shared__ char smraw[];
    __half* Xsh  = reinterpret_cast<__half*>(smraw + GA_XS_B);
    float*  sa   = reinterpret_cast<float*>(smraw + GA_SA_B);
    float*  Wgfs = reinterpret_cast<float*>(smraw + GA_WG_B);
    __half* Wb0  = reinterpret_cast<__half*>(smraw + GA_WB_B);
    __half* Wb1  = reinterpret_cast<__half*>(smraw + GA_WB1_B);
    __half* Msh  = reinterpret_cast<__half*>(smraw + GA_WB_B);
    int a0 = blockIdx.x * 64;
    int tid = threadIdx.x;
    int lane = tid & 31, warp = tid >> 5;
    int gid = lane >> 2, tig = lane & 3;
    int wm = warp >> 3, wn = warp & 7;

    for (int i = tid; i < 64 * 16; i += 512) {
        int r = i >> 4, u = i & 15;
        int n = a0 + r; if (n >= N) n = N - 1;
        cpa16(Xsh + r * GXP + u * 8, g_embh + (size_t)n * 128 + u * 8);
    }
    for (int i = tid; i < 64 * 16; i += 512) {
        int r = i >> 4, c4 = i & 15;
        int n = a0 + r; if (n >= N) n = N - 1;
        cpa16(sa + r * 64 + c4 * 4, g_acc + (size_t)n * 64 + c4 * 4);
    }
    for (int i = tid; i < 16 * 32; i += 512) {
        cpa16(Wgfs + i * 4, Wgf + i * 4);
    }
    for (int i = tid; i < 512 * 4; i += 512) {
        int r = i >> 2, u = i & 3;
        cpa16(Wb0 + r * GBP + u * 8, g_aghh + (size_t)r * 128 + u * 8);
    }
    CP_COMMIT();
    for (int i = tid; i < 512 * 4; i += 512) {
        int r = i >> 2, u = i & 3;
        cpa16(Wb1 + r * GBP + u * 8, g_aghh + (size_t)r * 128 + 32 + u * 8);
    }
    CP_COMMIT();

    float acc[2][8][4];
    #pragma unroll
    for (int mt = 0; mt < 2; mt++)
        #pragma unroll
        for (int nt = 0; nt < 8; nt++)
            #pragma unroll
            for (int e = 0; e < 4; e++) acc[mt][nt][e] = 0.f;

    for (int c = 0; c < 4; c++) {
        CP_WAIT1();
        __syncthreads();
        __half* wb = (c & 1) ? Wb1 : Wb0;
        #pragma unroll
        for (int ks = 0; ks < 32; ks += 16) {
            int kg = c * 32 + ks;
            uint32_t A[2][4];
            #pragma unroll
            for (int mt = 0; mt < 2; mt++) {
                int row = 32 * wm + 16 * mt + gid;
                A[mt][0] = h2u(&Xsh[row * GXP + kg + tig * 2]);
                A[mt][1] = h2u(&Xsh[(row + 8) * GXP + kg + tig * 2]);
                A[mt][2] = h2u(&Xsh[row * GXP + kg + tig * 2 + 8]);
                A[mt][3] = h2u(&Xsh[(row + 8) * GXP + kg + tig * 2 + 8]);
            }
            #pragma unroll
            for (int nt = 0; nt < 8; nt++) {
                int nn = 64 * wn + 8 * nt + gid;
                uint32_t B[2];
                B[0] = h2u(&wb[nn * GBP + ks + tig * 2]);
                B[1] = h2u(&wb[nn * GBP + ks + tig * 2 + 8]);
                mma_f16(acc[0][nt], A[0], B);
                mma_f16(acc[1][nt], A[1], B);
            }
        }
        __syncthreads();
        if (c + 2 < 4) {
            __half* dst = (c & 1) ? Wb1 : Wb0;
            for (int i = tid; i < 512 * 4; i += 512) {
                int r = i >> 2, u = i & 3;
                cpa16(dst + r * GBP + u * 8,
                      g_aghh + (size_t)r * 128 + (c + 2) * 32 + u * 8);
            }
        }
        CP_COMMIT();
    }

    #pragma unroll
    for (int mt = 0; mt < 2; mt++) {
        int r0 = 32 * wm + 16 * mt + gid;
        #pragma unroll
        for (int nt = 0; nt < 8; nt++) {
            int col = 64 * wn + 8 * nt + 2 * tig;
            *reinterpret_cast<__half2*>(&Msh[r0 * GMP + col]) =
                __floats2half2_rn(acc[mt][nt][0], acc[mt][nt][1]);
            *reinterpret_cast<__half2*>(&Msh[(r0 + 8) * GMP + col]) =
                __floats2half2_rn(acc[mt][nt][2], acc[mt][nt][3]);
        }
    }
    __syncthreads();

    for (int idx = tid; idx < 64 * 64; idx += 512) {
        int r = idx >> 6, f2 = idx & 63;
        int n = a0 + r;
        if (n >= N) continue;
        int f = 2 * f2;
        float m0 = 0.f, m1 = 0.f;
        #pragma unroll
        for (int g = 0; g < 16; g++) {
            float s = sa[r * 64 + g];
            m0 += s * Wgfs[g * 128 + f];
            m1 += s * Wgfs[g * 128 + f + 1];
        }
        float e0 = __half2float(Xsh[r * GXP + f]);
        float e1 = __half2float(Xsh[r * GXP + f + 1]);
        float qq = q[n];
        __half* msg = g_msgh + (size_t)n * 288;
        *reinterpret_cast<__half2*>(&msg[f])       = __floats2half2_rn(e0 * m0, e1 * m1);
        *reinterpret_cast<__half2*>(&msg[160 + f]) = __floats2half2_rn(qq * m0, qq * m1);
    }
    for (int idx = tid; idx < 64 * 32; idx += 512) {
        int r = idx >> 5, h = idx & 31;
        int n = a0 + r;
        if (n >= N) continue;
        float v0 = 0.f, v1 = 0.f, v2 = 0.f;
        #pragma unroll
        for (int g = 0; g < 16; g++) {
            float Mv = __half2float(Msh[r * GMP + g * 32 + h]);
            v0 += sa[r * 64 + 16 + g] * Mv;
            v1 += sa[r * 64 + 32 + g] * Mv;
            v2 += sa[r * 64 + 48 + g] * Mv;
        }
        float sq = v0 * v0 + v1 * v1 + v2 * v2;
        g_msgh[(size_t)n * 288 + 128 + h] = __float2half((sq > 0.f) ? sqrtf(sq) : 0.f);
    }
}

// ---------------------------------------------------------------------------
// Launch 4 (PROFILED): Layer 1, fp16, 128-atom tiles (R14 config, 43.8us).
// ---------------------------------------------------------------------------
#define L1KP 296
#define L1_OX (256 * L1KP)
#define L1_SMEM ((L1_OX + 128 * L1KP) * 2)

__global__ void __launch_bounds__(512, 1) k_l1(const float* __restrict__ b1, int N) {
    extern __shared__ __half smh[];
    __half* W  = smh;
    __half* Xs = smh + L1_OX;
    int tid = threadIdx.x;
    int lane = tid & 31, warp = tid >> 5;
    int gid = lane >> 2, tig = lane & 3;
    int wm = warp >> 2, wn = warp & 3;

    for (int i = tid; i < 256 * 36; i += 512) {
        int r = i / 36, u = i - r * 36;
        cpa16(W + r * L1KP + u * 8, g_w1h + (size_t)r * 288 + u * 8);
    }
    CP_COMMIT();

    int tiles = (N + 127) >> 7;
    for (int t = blockIdx.x; t < tiles; t += gridDim.x) {
        int a0 = t * 128;
        __syncthreads();
        for (int i = tid; i < 128 * 36; i += 512) {
            int r = i / 36, u = i - r * 36;
            int n = a0 + r; if (n >= N) n = N - 1;
            cpa16(Xs + r * L1KP + u * 8, g_msgh + (size_t)n * 288 + u * 8);
        }
        CP_COMMIT(); CP_WAIT0();
        __syncthreads();

        float acc[2][8][4];
        #pragma unroll
        for (int mt = 0; mt < 2; mt++)
            #pragma unroll
            for (int nt = 0; nt < 8; nt++)
                #pragma unroll
                for (int e = 0; e < 4; e++) acc[mt][nt][e] = 0.f;

        #pragma unroll 2
        for (int kg = 0; kg < 288; kg += 16) {
            uint32_t A[2][4];
            #pragma unroll
            for (int mt = 0; mt < 2; mt++) {
                int row = 32 * wm + 16 * mt + gid;
                A[mt][0] = h2u(&Xs[row * L1KP + kg + tig * 2]);
                A[mt][1] = h2u(&Xs[(row + 8) * L1KP + kg + tig * 2]);
                A[mt][2] = h2u(&Xs[row * L1KP + kg + tig * 2 + 8]);
                A[mt][3] = h2u(&Xs[(row + 8) * L1KP + kg + tig * 2 + 8]);
            }
            #pragma unroll
            for (int nt = 0; nt < 8; nt++) {
                int nn = 64 * wn + 8 * nt + gid;
                uint32_t B[2];
                B[0] = h2u(&W[nn * L1KP + kg + tig * 2]);
                B[1] = h2u(&W[nn * L1KP + kg + tig * 2 + 8]);
                mma_f16(acc[0][nt], A[0], B);
                mma_f16(acc[1][nt], A[1], B);
            }
        }

        #pragma unroll
        for (int mt = 0; mt < 2; mt++) {
            int row0 = 32 * wm + 16 * mt + gid;
            int n0 = a0 + row0, n1 = n0 + 8;
            #pragma unroll
            for (int nt = 0; nt < 8; nt++) {
                int col = 64 * wn + 8 * nt + 2 * tig;
                float bb0 = b1[col], bb1 = b1[col + 1];
                if (n0 < N)
                    *reinterpret_cast<__half2*>(&g_h1h[(size_t)n0 * 256 + col]) =
                        __floats2half2_rn(gelu_exact(acc[mt][nt][0] + bb0),
                                          gelu_exact(acc[mt][nt][1] + bb1));
                if (n1 < N)
                    *reinterpret_cast<__half2*>(&g_h1h[(size_t)n1 * 256 + col]) =
                        __floats2half2_rn(gelu_exact(acc[mt][nt][2] + bb0),
                                          gelu_exact(acc[mt][nt][3] + bb1));
            }
        }
    }
}

// ---------------------------------------------------------------------------
// Launch 5: merged Layers 2+3, double-buffered acts (R15 config).
// ---------------------------------------------------------------------------
#define L2KP 264
#define L3KP 136
#define M23_W2 0
#define M23_W3 (128 * L2KP)
#define M23_X0 (M23_W3 + 136 * L3KP)
#define M23_X1 (M23_X0 + 64 * L2KP)
#define M23_H2 (M23_X1 + 64 * L2KP)
#define M23_SMEM ((M23_H2 + 64 * L3KP) * 2)

__device__ __forceinline__ void l23_stage(__half* dst, int t, int N) {
    int a0 = t * 64;
    for (int i = threadIdx.x; i < 64 * 32; i += 512) {
        int r = i >> 5, u = i & 31;
        int n = a0 + r; if (n >= N) n = N - 1;
        cpa16(dst + r * L2KP + u * 8, g_h1h + (size_t)n * 256 + u * 8);
    }
}

__global__ void __launch_bounds__(512, 1) k_l23(const float* __restrict__ b2,
                                                const float* __restrict__ b3,
                                                float* __restrict__ out, int N) {
    extern __shared__ __half smh[];
    __half* W2 = smh + M23_W2;
    __half* W3 = smh + M23_W3;
    __half* X0 = smh + M23_X0;
    __half* X1 = smh + M23_X1;
    __half* H2 = smh + M23_H2;
    int tid = threadIdx.x;
    int lane = tid & 31, warp = tid >> 5;
    int gid = lane >> 2, tig = lane & 3;
    int wm = warp >> 3, wn = warp & 7;

    for (int i = tid; i < 128 * 32; i += 512) {
        int r = i >> 5, u = i & 31;
        cpa16(W2 + r * L2KP + u * 8, g_w2h + (size_t)r * 256 + u * 8);
    }
    for (int i = tid; i < 136 * 16; i += 512) {
        int r = i >> 4, u = i & 15;
        cpa16(W3 + r * L3KP + u * 8, g_w3h + (size_t)r * 128 + u * 8);
    }
    CP_COMMIT();

    int tiles = (N + 63) >> 6;
    if (blockIdx.x < tiles) l23_stage(X0, blockIdx.x, N);
    CP_COMMIT();
    if (blockIdx.x + 148 < tiles) l23_stage(X1, blockIdx.x + 148, N);
    CP_COMMIT();

    size_t dq_off = (size_t)N * 128;
    size_t f_off = dq_off + (size_t)N;
    int it = 0;
    for (int t = blockIdx.x; t < tiles; t += 148, it++) {
        CP_WAIT1();
        __syncthreads();
        __half* Xs = (it & 1) ? X1 : X0;
        int a0 = t * 64;

        float acc[2][2][4];
        #pragma unroll
        for (int mt = 0; mt < 2; mt++)
            #pragma unroll
            for (int nt = 0; nt < 2; nt++)
                #pragma unroll
                for (int e = 0; e < 4; e++) acc[mt][nt][e] = 0.f;

        #pragma unroll 2
        for (int kg = 0; kg < 256; kg += 16) {
            uint32_t A[2][4];
            #pragma unroll
            for (int mt = 0; mt < 2; mt++) {
                int row = 32 * wm + 16 * mt + gid;
                A[mt][0] = h2u(&Xs[row * L2KP + kg + tig * 2]);
                A[mt][1] = h2u(&Xs[(row + 8) * L2KP + kg + tig * 2]);
                A[mt][2] = h2u(&Xs[row * L2KP + kg + tig * 2 + 8]);
                A[mt][3] = h2u(&Xs[(row + 8) * L2KP + kg + tig * 2 + 8]);
            }
            #pragma unroll
            for (int nt = 0; nt < 2; nt++) {
                int nn = 16 * wn + 8 * nt + gid;
                uint32_t B[2];
                B[0] = h2u(&W2[nn * L2KP + kg + tig * 2]);
                B[1] = h2u(&W2[nn * L2KP + kg + tig * 2 + 8]);
                mma_f16(acc[0][nt], A[0], B);
                mma_f16(acc[1][nt], A[1], B);
            }
        }
        #pragma unroll
        for (int mt = 0; mt < 2; mt++) {
            int row0 = 32 * wm + 16 * mt + gid;
            #pragma unroll
            for (int nt = 0; nt < 2; nt++) {
                int col = 16 * wn + 8 * nt + 2 * tig;
                float bb0 = b2[col], bb1 = b2[col + 1];
                *reinterpret_cast<__half2*>(&H2[row0 * L3KP + col]) =
                    __floats2half2_rn(gelu_exact(acc[mt][nt][0] + bb0),
                                      gelu_exact(acc[mt][nt][1] + bb1));
                *reinterpret_cast<__half2*>(&H2[(row0 + 8) * L3KP + col]) =
                    __floats2half2_rn(gelu_exact(acc[mt][nt][2] + bb0),
                                      gelu_exact(acc[mt][nt][3] + bb1));
            }
        }
        __syncthreads();
        int tn = t + 2 * 148;
        if (tn < tiles) l23_stage(Xs, tn, N);
        CP_COMMIT();

        float d3[5][4];
        #pragma unroll
        for (int tt = 0; tt < 5; tt++)
            #pragma unroll
            for (int e = 0; e < 4; e++) d3[tt][e] = 0.f;

        #pragma unroll
        for (int tt = 0; tt < 5; tt++) {
            int tw = warp + 16 * tt;
            if (tw >= 68) break;
            int m0 = 16 * (tw & 3), n0 = 8 * (tw >> 2);
            #pragma unroll
            for (int kg = 0; kg < 128; kg += 16) {
                uint32_t A[4], B[2];
                A[0] = h2u(&H2[(m0 + gid) * L3KP + kg + tig * 2]);
                A[1] = h2u(&H2[(m0 + 8 + gid) * L3KP + kg + tig * 2]);
                A[2] = h2u(&H2[(m0 + gid) * L3KP + kg + tig * 2 + 8]);
                A[3] = h2u(&H2[(m0 + 8 + gid) * L3KP + kg + tig * 2 + 8]);
                B[0] = h2u(&W3[(n0 + gid) * L3KP + kg + tig * 2]);
                B[1] = h2u(&W3[(n0 + gid) * L3KP + kg + tig * 2 + 8]);
                mma_f16(d3[tt], A, B);
            }
        }

        #pragma unroll
        for (int tt = 0; tt < 5; tt++) {
            int tw = warp + 16 * tt;
            if (tw >= 68) break;
            int m0 = 16 * (tw & 3), n0 = 8 * (tw >> 2);
            #pragma unroll
            for (int e = 0; e < 4; e++) {
                int row = m0 + gid + ((e >> 1) ? 8 : 0);
                int j = n0 + 2 * tig + (e & 1);
                int n = a0 + row;
                if (n >= N || j >= 130) continue;
                float v = d3[tt][e] + b3[j];
                if (j == 0)      out[dq_off + n] = v;
                else if (j == 1) out[f_off + n] = v;
                else             out[(size_t)n * 128 + (j - 2)] = v;
            }
        }
    }
}

// ---------------------------------------------------------------------------
extern "C" void kernel_launch(void* const* d_in, const int* in_sizes, int n_in,
                              void* d_out, int out_size) {
    const float* emb  = (const float*)d_in[0];
    const float* q    = (const float*)d_in[1];
    const int*   pidx = (const int*)d_in[2];
    const float* gs   = (const float*)d_in[3];
    const float* gv   = (const float*)d_in[4];
    const float* agh  = (const float*)d_in[5];
    const float* Wgf  = (const float*)d_in[6];
    const float* W1   = (const float*)d_in[7];
    const float* b1   = (const float*)d_in[8];
    const float* W2   = (const float*)d_in[9];
    const float* b2   = (const float*)d_in[10];
    const float* W3   = (const float*)d_in[11];
    const float* b3   = (const float*)d_in[12];
    float* out = (float*)d_out;

    int N = in_sizes[0] / 128;
    int P = in_sizes[2] / 2;
    if (N > NMAX) N = NMAX;
    const int* idxj = pidx + P;

    // 1: zero accumulators
    k_zero<<<(N * 16 + 255) / 256, 256>>>(N);

    // 2: merged scatter (2 quads/thread) + conversions
    long long Q = (long long)P * 16;
    int SB = (int)((Q + 511) / 512);
    int CB = (CVT_W + N * 128 + 255) / 256;
    k_scatter_cvt<<<SB + CB, 256>>>(idxj, gs, gv, P, SB, agh, W1, W2, W3, emb, N);

    // 3: fused GEMM-M + assemble
    cudaFuncSetAttribute(k_gemm_assemble, cudaFuncAttributeMaxDynamicSharedMemorySize, GA_SMEM);
    k_gemm_assemble<<<(N + 63) / 64, 512, GA_SMEM>>>(q, Wgf, N);

    // 4 (profiled): layer 1 (R14 config)
    cudaFuncSetAttribute(k_l1, cudaFuncAttributeMaxDynamicSharedMemorySize, L1_SMEM);
    k_l1<<<148, 512, L1_SMEM>>>(b1, N);

    // 5: merged layers 2+3, double-buffered acts
    cudaFuncSetAttribute(k_l23, cudaFuncAttributeMaxDynamicSharedMemorySize, M23_SMEM);
    k_l23<<<148, 512, M23_SMEM>>>(b2, b3, out, N);
}